// round 11
// baseline (speedup 1.0000x reference)
#include <cuda_runtime.h>

#define NN 2048
#define LOG2F_ 0.69314718055994530942f

typedef unsigned long long ull;

// Scratch (__device__ globals; no cudaMalloc allowed)
__device__ __align__(16) float g_M1T[32 * NN];   // [u][n] averaged em1, transposed
__device__ __align__(16) ull   g_A2[32 * NN];    // [u][n] averaged em2, DUP pairs (v,v)
__device__ float g_partial[8 * NN];              // softplus row-sums per j-eighth
__device__ float g_diag[NN];                     // raw u_ii
__device__ unsigned g_ticket = 0;                // last-block ticket (monotone, %512)

// ---- packed f32x2 helpers (FFMA2 only reachable via PTX fma.rn.f32x2) ----
__device__ __forceinline__ ull pack2(float x, float y) {
    ull r;
    asm("mov.b64 %0, {%1, %2};" : "=l"(r) : "r"(__float_as_uint(x)), "r"(__float_as_uint(y)));
    return r;
}
__device__ __forceinline__ void unpack2(ull v, float& x, float& y) {
    unsigned lo, hi;
    asm("mov.b64 {%0, %1}, %2;" : "=r"(lo), "=r"(hi) : "l"(v));
    x = __uint_as_float(lo); y = __uint_as_float(hi);
}
__device__ __forceinline__ ull ffma2(ull a, ull b, ull c) {
    ull d;
    asm("fma.rn.f32x2 %0, %1, %2, %3;" : "=l"(d) : "l"(a), "l"(b), "l"(c));
    return d;
}

// stable softplus(x) = max(x,0) + log(1 + exp(-|x|))
__device__ __forceinline__ float softplus_f(float x) {
    float a = fabsf(x);
    float l = __logf(1.f + __expf(-a));
    return fmaxf(x, 0.f) + l;
}

// ---- embed smem layout (static 45.3KB, aliased regions) ----
#define SM_IN    0
#define SM_SP1   10240
#define SM_SP2   26624
#define SM_PART  34816
#define SM_SB1   45056
#define SM_SB2   45184
#define SM_TOTAL 45312

// ---------------------------------------------------------------------------
// Kernel 1 (v5, unchanged from R10): embeddings + leaky_relu + agent-mean.
// Inputs staged through smem; inner loop = LDS + FFMA2 only.
// ---------------------------------------------------------------------------
__global__ void __launch_bounds__(256) embed_kernel(
    const float* __restrict__ state, const float* __restrict__ action,
    const float* __restrict__ W1, const float* __restrict__ b1,
    const float* __restrict__ W2, const float* __restrict__ b2) {
    __shared__ __align__(16) char smem[SM_TOTAL];
    float* sIN = (float*)(smem + SM_IN);
    ull   (*sP1)[32] = (ull (*)[32])(smem + SM_SP1);
    ull   (*sP2)[32] = (ull (*)[32])(smem + SM_SP2);
    float (*spart)[4][5][32] = (float (*)[4][5][32])(smem + SM_PART);
    float* sb1 = (float*)(smem + SM_SB1);
    float* sb2 = (float*)(smem + SM_SB2);

    const int tid = threadIdx.x;

    #pragma unroll
    for (int i = 0; i < 8; i++) {
        int idx = tid + i * 256;
        int k2 = idx >> 5, u = idx & 31;
        sP1[k2][u] = pack2(W1[k2 * 64 + u], W1[k2 * 64 + 32 + u]);
    }
    #pragma unroll
    for (int i = 0; i < 4; i++) {
        int idx = tid + i * 256;
        int k2 = idx >> 5, u = idx & 31;
        sP2[k2][u] = pack2(W2[k2 * 64 + u], W2[k2 * 64 + 32 + u]);
    }
    {   // stage state tile: 4 samples x 640 floats, coalesced
        const float4* sg = (const float4*)(state + (size_t)blockIdx.x * 2560);
        float4* si4 = (float4*)sIN;
        si4[tid]       = sg[tid];
        si4[tid + 256] = sg[tid + 256];
        if (tid < 128) si4[tid + 512] = sg[tid + 512];
    }
    if (tid < 32) { sb1[tid] = b1[tid]; sb2[tid] = b2[tid]; }
    __syncthreads();

    const int nl = tid >> 6, kq = (tid >> 4) & 3, uh = tid & 15;
    const int n8 = blockIdx.x * 4;

    // ---------------- GEMM1: state @ W1, K-quarter (32 of 128) ------------
    {
        const float* base = sIN + nl * 640 + kq * 32;
        ull acc[5][2];
        #pragma unroll
        for (int a = 0; a < 5; a++) { acc[a][0] = 0ull; acc[a][1] = 0ull; }

        #pragma unroll
        for (int k4 = 0; k4 < 8; k4++) {
            ulonglong2 x[5];
            #pragma unroll
            for (int a = 0; a < 5; a++)
                x[a] = *(const ulonglong2*)(base + a * 128 + k4 * 4);
            const int k2 = kq * 16 + k4 * 2;
            ulonglong2 w0 = *(const ulonglong2*)&sP1[k2][2 * uh];
            ulonglong2 w1 = *(const ulonglong2*)&sP1[k2 + 1][2 * uh];
            #pragma unroll
            for (int a = 0; a < 5; a++) {
                acc[a][0] = ffma2(x[a].x, w0.x, acc[a][0]);
                acc[a][0] = ffma2(x[a].y, w1.x, acc[a][0]);
                acc[a][1] = ffma2(x[a].x, w0.y, acc[a][1]);
                acc[a][1] = ffma2(x[a].y, w1.y, acc[a][1]);
            }
        }
        #pragma unroll
        for (int a = 0; a < 5; a++) {
            float x0, x1, y0, y1;
            unpack2(acc[a][0], x0, x1);
            unpack2(acc[a][1], y0, y1);
            *(float2*)&spart[nl][kq][a][2 * uh] = make_float2(x0 + x1, y0 + y1);
        }
    }
    __syncthreads();

    // finalize1 (threads 0..127) + restage action (threads 128..255)
    if (tid < 128) {
        const int fu = tid >> 2, fnl = tid & 3;
        const int fn = n8 + fnl;
        float m = 0.f;
        #pragma unroll
        for (int a = 0; a < 5; a++) {
            float v = sb1[fu];
            #pragma unroll
            for (int q = 0; q < 4; q++) v += spart[fnl][q][a][fu];
            m += (v > 0.f) ? v : 0.01f * v;          // leaky_relu(0.01)
        }
        g_M1T[fu * NN + fn] = 0.2f * m;
    } else {
        const int t = tid - 128;
        const float4* ag = (const float4*)(action + (size_t)blockIdx.x * 1280);
        float4* si4 = (float4*)sIN;
        si4[t]       = ag[t];
        si4[t + 128] = ag[t + 128];
        if (t < 64) si4[t + 256] = ag[t + 256];
    }
    __syncthreads();

    // ---------------- GEMM2: action @ W2, K-quarter (16 of 64) ------------
    {
        const float* base = sIN + nl * 320 + kq * 16;
        ull acc[5][2];
        #pragma unroll
        for (int a = 0; a < 5; a++) { acc[a][0] = 0ull; acc[a][1] = 0ull; }

        #pragma unroll
        for (int k4 = 0; k4 < 4; k4++) {
            ulonglong2 x[5];
            #pragma unroll
            for (int a = 0; a < 5; a++)
                x[a] = *(const ulonglong2*)(base + a * 64 + k4 * 4);
            const int k2 = kq * 8 + k4 * 2;
            ulonglong2 w0 = *(const ulonglong2*)&sP2[k2][2 * uh];
            ulonglong2 w1 = *(const ulonglong2*)&sP2[k2 + 1][2 * uh];
            #pragma unroll
            for (int a = 0; a < 5; a++) {
                acc[a][0] = ffma2(x[a].x, w0.x, acc[a][0]);
                acc[a][0] = ffma2(x[a].y, w1.x, acc[a][0]);
                acc[a][1] = ffma2(x[a].x, w0.y, acc[a][1]);
                acc[a][1] = ffma2(x[a].y, w1.y, acc[a][1]);
            }
        }
        __syncthreads();
        #pragma unroll
        for (int a = 0; a < 5; a++) {
            float x0, x1, y0, y1;
            unpack2(acc[a][0], x0, x1);
            unpack2(acc[a][1], y0, y1);
            *(float2*)&spart[nl][kq][a][2 * uh] = make_float2(x0 + x1, y0 + y1);
        }
    }
    __syncthreads();

    if (tid < 128) {
        const int fu = tid >> 2, fnl = tid & 3;
        const int fn = n8 + fnl;
        float m = 0.f;
        #pragma unroll
        for (int a = 0; a < 5; a++) {
            float v = sb2[fu];
            #pragma unroll
            for (int q = 0; q < 4; q++) v += spart[fnl][q][a][fu];
            m += (v > 0.f) ? v : 0.01f * v;
        }
        float s2 = 0.2f * m;
        g_A2[fu * NN + fn] = pack2(s2, s2);          // pre-duplicated pair
    }
}

// ---------------------------------------------------------------------------
// Kernel 2 (v5): fused GEMM (u[i,j]=M2[i].M1[j], K=32) + batched softplus
// row-sums + last-block finalize. OCCUPANCY-FIRST redesign:
//   grid 512 = 64 i-tiles(32 rows) x 8 chunks(256 cols); one chunk per block
//   (no inner loop, no register prefetch), launch_bounds(256,4) caps regs at
//   64 -> 4 blocks/SM, occ ~50%; inter-block overlap hides stage latency.
// Warp = 4 i-rows (A broadcast); thread tile 4i x 8j, conflict-free LDS.128.
// Softplus batched per 8 elems: sum(max(x,0)) + log(prod(1+exp(-|x|))),
// factors in (1,2] so prod <= 256 (no overflow) -> LG2 count / 8.
// ---------------------------------------------------------------------------
__global__ void __launch_bounds__(256, 4) jsd_kernel(float* __restrict__ out) {
    __shared__ __align__(16) ull sA2[32][32];        // 8 KB [u][ii] dup pairs
    __shared__ __align__(16) float sB[32][256];      // 32 KB B chunk
    __shared__ unsigned s_last;

    const int tid = threadIdx.x;
    const int ib = blockIdx.x >> 3, q = blockIdx.x & 7;
    const int i0 = ib * 32, j0 = q * 256;
    const int ti = tid >> 5, tj = tid & 31;          // warp id = ti

    #pragma unroll
    for (int t = 0; t < 4; t++) {                    // stage A dup pairs
        int idx = tid + t * 256;                     // 0..1023
        int u = idx >> 5, ii = idx & 31;
        sA2[u][ii] = g_A2[u * NN + i0 + ii];
    }
    #pragma unroll
    for (int t = 0; t < 8; t++) {                    // stage B chunk (direct)
        int idx = tid + t * 256;                     // 0..2047
        int u = idx >> 6, f = (idx & 63) * 4;
        *(float4*)&sB[u][f] = *(const float4*)&g_M1T[u * NN + j0 + f];
    }
    __syncthreads();

    ull acc[4][4];
    #pragma unroll
    for (int r = 0; r < 4; r++)
        #pragma unroll
        for (int p = 0; p < 4; p++) acc[r][p] = 0ull;

    #pragma unroll 8
    for (int u = 0; u < 32; u++) {
        ulonglong2 ad0 = *(const ulonglong2*)&sA2[u][ti * 4];      // rows 0,1
        ulonglong2 ad1 = *(const ulonglong2*)&sA2[u][ti * 4 + 2];  // rows 2,3
        ulonglong2 b0  = *(const ulonglong2*)&sB[u][tj * 4];
        ulonglong2 b1  = *(const ulonglong2*)&sB[u][128 + tj * 4];
        acc[0][0] = ffma2(ad0.x, b0.x, acc[0][0]);
        acc[0][1] = ffma2(ad0.x, b0.y, acc[0][1]);
        acc[0][2] = ffma2(ad0.x, b1.x, acc[0][2]);
        acc[0][3] = ffma2(ad0.x, b1.y, acc[0][3]);
        acc[1][0] = ffma2(ad0.y, b0.x, acc[1][0]);
        acc[1][1] = ffma2(ad0.y, b0.y, acc[1][1]);
        acc[1][2] = ffma2(ad0.y, b1.x, acc[1][2]);
        acc[1][3] = ffma2(ad0.y, b1.y, acc[1][3]);
        acc[2][0] = ffma2(ad1.x, b0.x, acc[2][0]);
        acc[2][1] = ffma2(ad1.x, b0.y, acc[2][1]);
        acc[2][2] = ffma2(ad1.x, b1.x, acc[2][2]);
        acc[2][3] = ffma2(ad1.x, b1.y, acc[2][3]);
        acc[3][0] = ffma2(ad1.y, b0.x, acc[3][0]);
        acc[3][1] = ffma2(ad1.y, b0.y, acc[3][1]);
        acc[3][2] = ffma2(ad1.y, b1.x, acc[3][2]);
        acc[3][3] = ffma2(ad1.y, b1.y, acc[3][3]);
    }

    // epilogue: diag capture + batched softplus row sums
    const bool qmatch = (q == (i0 >> 8));            // chunk containing diag
    float rowsum[4];
    #pragma unroll
    for (int r = 0; r < 4; r++) {
        const int ig = i0 + ti * 4 + r;
        float lin = 0.f, prod = 1.f;
        #pragma unroll
        for (int p = 0; p < 4; p++) {
            float x0, x1;
            unpack2(acc[r][p], x0, x1);
            if (qmatch) {
                int col = j0 + ((p < 2) ? (tj * 4 + p * 2)
                                        : (128 + tj * 4 + (p - 2) * 2));
                if (col == ig)     g_diag[ig] = x0;  // single writer
                if (col + 1 == ig) g_diag[ig] = x1;
            }
            lin  += fmaxf(x0, 0.f) + fmaxf(x1, 0.f);
            prod *= (1.f + __expf(-fabsf(x0))) * (1.f + __expf(-fabsf(x1)));
        }
        rowsum[r] = lin + __logf(prod);              // sum of 8 softplus
    }

    #pragma unroll
    for (int r = 0; r < 4; r++) {                    // rows within one warp
        float v = rowsum[r];
        v += __shfl_down_sync(0xffffffffu, v, 16);
        v += __shfl_down_sync(0xffffffffu, v, 8);
        v += __shfl_down_sync(0xffffffffu, v, 4);
        v += __shfl_down_sync(0xffffffffu, v, 2);
        v += __shfl_down_sync(0xffffffffu, v, 1);
        if (tj == 0) g_partial[q * NN + i0 + ti * 4 + r] = v;
    }

    // ---- last-block finalize (threadFenceReduction pattern) ----
    __threadfence();                                 // publish partials + diag
    __syncthreads();
    if (tid == 0) {
        unsigned old = atomicAdd(&g_ticket, 1u);
        s_last = ((old & 511u) == 511u) ? 1u : 0u;   // grid == 512 exactly
    }
    __syncthreads();
    if (s_last) {
        __threadfence();                             // acquire others' writes
        #pragma unroll
        for (int r = 0; r < 8; r++) {
            const int i = tid + r * 256;
            float tot = 0.f;
            #pragma unroll
            for (int qq = 0; qq < 8; qq++) tot += g_partial[qq * NN + i];
            float ud  = g_diag[i];
            float spd = softplus_f(ud);
            float Eneg = (tot - spd - 2047.f * LOG2F_) * (1.f / 2047.f);
            float Epos = LOG2F_ - spd + ud;          // = log2 - softplus(-u_ii)
            out[i]      = Eneg - Epos;               // loss
            out[NN + i] = Epos;                      // MI
        }
    }
}

extern "C" void kernel_launch(void* const* d_in, const int* in_sizes, int n_in,
                              void* d_out, int out_size) {
    const float* state  = (const float*)d_in[0];
    const float* action = (const float*)d_in[1];
    const float* W1     = (const float*)d_in[2];
    const float* b1     = (const float*)d_in[3];
    const float* W2     = (const float*)d_in[4];
    const float* b2     = (const float*)d_in[5];
    float* out = (float*)d_out;

    embed_kernel<<<NN / 4, 256>>>(state, action, W1, b1, W2, b2);
    jsd_kernel<<<512, 256>>>(out);
}

// round 13
// speedup vs baseline: 1.2280x; 1.2280x over previous
#include <cuda_runtime.h>
#include <cuda_bf16.h>

#define NN 2048
#define LOG2F_ 0.69314718055994530942f

typedef unsigned long long ull;

// Scratch (__device__ globals; no cudaMalloc allowed)
// hi/lo split bf16 rows: [n][0..31]=hi(u), [n][32..63]=lo(u) -> 128B rows.
// Full K=64 bf16 dot == hi.hi + hi.lo + lo.hi + lo.lo ~= fp32 dot (lo.lo ~2^-16 rel).
__device__ __align__(16) __nv_bfloat16 g_Ahl[NN * 64];  // M2 (i side / MMA A)
__device__ __align__(16) __nv_bfloat16 g_Bhl[NN * 64];  // M1 (j side / MMA B)
__device__ float g_partial[16 * NN];  // [jtile][row] softplus row sums
__device__ float g_diag[NN];          // raw u_ii
__device__ unsigned g_ticket = 0;     // last-block ticket (monotone, %256)

// ---- packed f32x2 helpers ----
__device__ __forceinline__ ull pack2(float x, float y) {
    ull r;
    asm("mov.b64 %0, {%1, %2};" : "=l"(r) : "r"(__float_as_uint(x)), "r"(__float_as_uint(y)));
    return r;
}
__device__ __forceinline__ void unpack2(ull v, float& x, float& y) {
    unsigned lo, hi;
    asm("mov.b64 {%0, %1}, %2;" : "=r"(lo), "=r"(hi) : "l"(v));
    x = __uint_as_float(lo); y = __uint_as_float(hi);
}
__device__ __forceinline__ ull ffma2(ull a, ull b, ull c) {
    ull d;
    asm("fma.rn.f32x2 %0, %1, %2, %3;" : "=l"(d) : "l"(a), "l"(b), "l"(c));
    return d;
}
__device__ __forceinline__ float softplus_f(float x) {
    float a = fabsf(x);
    float l = __logf(1.f + __expf(-a));
    return fmaxf(x, 0.f) + l;
}

// warp-level bf16 tensor-core mma: D(16x8,f32) += A(16x16,bf16) x B(16x8,bf16)
__device__ __forceinline__ void mma16816(float* c, const unsigned* a,
                                         const unsigned* b) {
    asm volatile(
        "mma.sync.aligned.m16n8k16.row.col.f32.bf16.bf16.f32 "
        "{%0,%1,%2,%3}, {%4,%5,%6,%7}, {%8,%9}, {%0,%1,%2,%3};"
        : "+f"(c[0]), "+f"(c[1]), "+f"(c[2]), "+f"(c[3])
        : "r"(a[0]), "r"(a[1]), "r"(a[2]), "r"(a[3]), "r"(b[0]), "r"(b[1]));
}

// ---- embed smem layout (static 45.3KB, aliased regions) ----
#define SM_IN    0
#define SM_SP1   10240
#define SM_SP2   26624
#define SM_PART  34816
#define SM_SB1   45056
#define SM_SB2   45184
#define SM_TOTAL 45312

// ---------------------------------------------------------------------------
// Kernel 1 (v5 + bf16 hi/lo emit, unchanged from R12): embeddings +
// leaky_relu + agent-mean; finalize emits hi/lo bf16 rows for the MMA.
// ---------------------------------------------------------------------------
__global__ void __launch_bounds__(256) embed_kernel(
    const float* __restrict__ state, const float* __restrict__ action,
    const float* __restrict__ W1, const float* __restrict__ b1,
    const float* __restrict__ W2, const float* __restrict__ b2) {
    __shared__ __align__(16) char smem[SM_TOTAL];
    float* sIN = (float*)(smem + SM_IN);
    ull   (*sP1)[32] = (ull (*)[32])(smem + SM_SP1);
    ull   (*sP2)[32] = (ull (*)[32])(smem + SM_SP2);
    float (*spart)[4][5][32] = (float (*)[4][5][32])(smem + SM_PART);
    float* sb1 = (float*)(smem + SM_SB1);
    float* sb2 = (float*)(smem + SM_SB2);

    const int tid = threadIdx.x;

    #pragma unroll
    for (int i = 0; i < 8; i++) {
        int idx = tid + i * 256;
        int k2 = idx >> 5, u = idx & 31;
        sP1[k2][u] = pack2(W1[k2 * 64 + u], W1[k2 * 64 + 32 + u]);
    }
    #pragma unroll
    for (int i = 0; i < 4; i++) {
        int idx = tid + i * 256;
        int k2 = idx >> 5, u = idx & 31;
        sP2[k2][u] = pack2(W2[k2 * 64 + u], W2[k2 * 64 + 32 + u]);
    }
    {   // stage state tile: 4 samples x 640 floats, coalesced
        const float4* sg = (const float4*)(state + (size_t)blockIdx.x * 2560);
        float4* si4 = (float4*)sIN;
        si4[tid]       = sg[tid];
        si4[tid + 256] = sg[tid + 256];
        if (tid < 128) si4[tid + 512] = sg[tid + 512];
    }
    if (tid < 32) { sb1[tid] = b1[tid]; sb2[tid] = b2[tid]; }
    __syncthreads();

    const int nl = tid >> 6, kq = (tid >> 4) & 3, uh = tid & 15;
    const int n8 = blockIdx.x * 4;

    // ---------------- GEMM1: state @ W1, K-quarter (32 of 128) ------------
    {
        const float* base = sIN + nl * 640 + kq * 32;
        ull acc[5][2];
        #pragma unroll
        for (int a = 0; a < 5; a++) { acc[a][0] = 0ull; acc[a][1] = 0ull; }

        #pragma unroll
        for (int k4 = 0; k4 < 8; k4++) {
            ulonglong2 x[5];
            #pragma unroll
            for (int a = 0; a < 5; a++)
                x[a] = *(const ulonglong2*)(base + a * 128 + k4 * 4);
            const int k2 = kq * 16 + k4 * 2;
            ulonglong2 w0 = *(const ulonglong2*)&sP1[k2][2 * uh];
            ulonglong2 w1 = *(const ulonglong2*)&sP1[k2 + 1][2 * uh];
            #pragma unroll
            for (int a = 0; a < 5; a++) {
                acc[a][0] = ffma2(x[a].x, w0.x, acc[a][0]);
                acc[a][0] = ffma2(x[a].y, w1.x, acc[a][0]);
                acc[a][1] = ffma2(x[a].x, w0.y, acc[a][1]);
                acc[a][1] = ffma2(x[a].y, w1.y, acc[a][1]);
            }
        }
        #pragma unroll
        for (int a = 0; a < 5; a++) {
            float x0, x1, y0, y1;
            unpack2(acc[a][0], x0, x1);
            unpack2(acc[a][1], y0, y1);
            *(float2*)&spart[nl][kq][a][2 * uh] = make_float2(x0 + x1, y0 + y1);
        }
    }
    __syncthreads();

    // finalize1 (threads 0..127) + restage action (threads 128..255)
    if (tid < 128) {
        const int fu = tid >> 2, fnl = tid & 3;
        const int fn = n8 + fnl;
        float m = 0.f;
        #pragma unroll
        for (int a = 0; a < 5; a++) {
            float v = sb1[fu];
            #pragma unroll
            for (int q = 0; q < 4; q++) v += spart[fnl][q][a][fu];
            m += (v > 0.f) ? v : 0.01f * v;          // leaky_relu(0.01)
        }
        float v1 = 0.2f * m;
        __nv_bfloat16 h = __float2bfloat16(v1);
        g_Bhl[fn * 64 + fu]      = h;
        g_Bhl[fn * 64 + 32 + fu] = __float2bfloat16(v1 - __bfloat162float(h));
    } else {
        const int t = tid - 128;
        const float4* ag = (const float4*)(action + (size_t)blockIdx.x * 1280);
        float4* si4 = (float4*)sIN;
        si4[t]       = ag[t];
        si4[t + 128] = ag[t + 128];
        if (t < 64) si4[t + 256] = ag[t + 256];
    }
    __syncthreads();

    // ---------------- GEMM2: action @ W2, K-quarter (16 of 64) ------------
    {
        const float* base = sIN + nl * 320 + kq * 16;
        ull acc[5][2];
        #pragma unroll
        for (int a = 0; a < 5; a++) { acc[a][0] = 0ull; acc[a][1] = 0ull; }

        #pragma unroll
        for (int k4 = 0; k4 < 4; k4++) {
            ulonglong2 x[5];
            #pragma unroll
            for (int a = 0; a < 5; a++)
                x[a] = *(const ulonglong2*)(base + a * 64 + k4 * 4);
            const int k2 = kq * 8 + k4 * 2;
            ulonglong2 w0 = *(const ulonglong2*)&sP2[k2][2 * uh];
            ulonglong2 w1 = *(const ulonglong2*)&sP2[k2 + 1][2 * uh];
            #pragma unroll
            for (int a = 0; a < 5; a++) {
                acc[a][0] = ffma2(x[a].x, w0.x, acc[a][0]);
                acc[a][0] = ffma2(x[a].y, w1.x, acc[a][0]);
                acc[a][1] = ffma2(x[a].x, w0.y, acc[a][1]);
                acc[a][1] = ffma2(x[a].y, w1.y, acc[a][1]);
            }
        }
        __syncthreads();
        #pragma unroll
        for (int a = 0; a < 5; a++) {
            float x0, x1, y0, y1;
            unpack2(acc[a][0], x0, x1);
            unpack2(acc[a][1], y0, y1);
            *(float2*)&spart[nl][kq][a][2 * uh] = make_float2(x0 + x1, y0 + y1);
        }
    }
    __syncthreads();

    if (tid < 128) {
        const int fu = tid >> 2, fnl = tid & 3;
        const int fn = n8 + fnl;
        float m = 0.f;
        #pragma unroll
        for (int a = 0; a < 5; a++) {
            float v = sb2[fu];
            #pragma unroll
            for (int q = 0; q < 4; q++) v += spart[fnl][q][a][fu];
            m += (v > 0.f) ? v : 0.01f * v;
        }
        float v2 = 0.2f * m;
        __nv_bfloat16 h = __float2bfloat16(v2);
        g_Ahl[fn * 64 + fu]      = h;
        g_Ahl[fn * 64 + 32 + fu] = __float2bfloat16(v2 - __bfloat162float(h));
    }
}

// ---------------------------------------------------------------------------
// Kernel 2 (v7, mma.sync tensor core): u = A.B^T as K=64 bf16 GEMM.
// Grid 256 = 16 i-tiles(128) x 16 j-tiles(128). Block: stage A/B tiles
// (128 rows x 64 bf16, 144B padded stride -> conflict-free fragment LDS),
// warp w = rows w*16..+15, all 128 cols: 4 ksteps x 16 nblocks of
// mma.m16n8k16 (row.col). Fragments are contiguous b32 smem loads (K-major).
// Epilogue: batched softplus (1 LG2/32 vals), quad shfl-reduce, diag capture,
// last-block ticket finalize.
// ---------------------------------------------------------------------------
#define TSTRIDE 144
__global__ void __launch_bounds__(256) jsd_kernel(float* __restrict__ out) {
    __shared__ __align__(16) char sA[128 * TSTRIDE];   // 18 KB
    __shared__ __align__(16) char sB[128 * TSTRIDE];   // 18 KB
    __shared__ unsigned s_last;

    const int tid = threadIdx.x;
    const int w = tid >> 5, lane = tid & 31;
    const int ib = blockIdx.x >> 4, q = blockIdx.x & 15;
    const int i0 = ib * 128, j0 = q * 128;

    // stage tiles: row = idx>>3, 16B granule g = idx&7
    #pragma unroll
    for (int t = 0; t < 4; t++) {
        int idx = tid + t * 256;                     // 0..1023
        int row = idx >> 3, g = idx & 7;
        *(uint4*)(sA + row * TSTRIDE + g * 16) =
            *(const uint4*)&g_Ahl[(i0 + row) * 64 + g * 8];
        *(uint4*)(sB + row * TSTRIDE + g * 16) =
            *(const uint4*)&g_Bhl[(j0 + row) * 64 + g * 8];
    }
    __syncthreads();

    // accumulators: 16 nblocks x {c0,c1 (row rA), c2,c3 (row rA+8)}
    float acc[16][4];
    #pragma unroll
    for (int nb = 0; nb < 16; nb++)
        #pragma unroll
        for (int p = 0; p < 4; p++) acc[nb][p] = 0.f;

    const int grp = lane >> 2, four = lane & 3;      // fragment coords
    const char* arow0 = sA + (w * 16 + grp) * TSTRIDE + four * 4;
    const char* brow0 = sB + grp * TSTRIDE + four * 4;

    #pragma unroll
    for (int ks = 0; ks < 4; ks++) {                 // K = 4 x 16
        const int kb = ks * 32;                      // byte offset of kstep
        unsigned afr[4];
        afr[0] = *(const unsigned*)(arow0 + kb);               // row grp,   k lo-half
        afr[1] = *(const unsigned*)(arow0 + 8 * TSTRIDE + kb); // row grp+8
        afr[2] = *(const unsigned*)(arow0 + kb + 16);          // k hi-half
        afr[3] = *(const unsigned*)(arow0 + 8 * TSTRIDE + kb + 16);
        #pragma unroll
        for (int nb = 0; nb < 16; nb++) {
            unsigned bfr[2];
            const char* bp = brow0 + nb * 8 * TSTRIDE + kb;
            bfr[0] = *(const unsigned*)(bp);                   // k lo-half, col grp
            bfr[1] = *(const unsigned*)(bp + 16);              // k hi-half
            mma16816(acc[nb], afr, bfr);
        }
    }

    // epilogue: rows rA (c0,c1) and rA+8 (c2,c3); cols j0+nb*8+2*four+{0,1}
    const int rA = i0 + w * 16 + grp;
    const int rB = rA + 8;
    const bool dtile = (ib == q);
    float linA = 0.f, prodA = 1.f, linB = 0.f, prodB = 1.f;
    #pragma unroll
    for (int nb = 0; nb < 16; nb++) {
        const int col = j0 + nb * 8 + 2 * four;
        float c0 = acc[nb][0], c1 = acc[nb][1];
        float c2 = acc[nb][2], c3 = acc[nb][3];
        if (dtile) {
            if (col == rA)     g_diag[rA] = c0;      // single writer each
            if (col + 1 == rA) g_diag[rA] = c1;
            if (col == rB)     g_diag[rB] = c2;
            if (col + 1 == rB) g_diag[rB] = c3;
        }
        linA  += fmaxf(c0, 0.f) + fmaxf(c1, 0.f);
        prodA *= (1.f + __expf(-fabsf(c0))) * (1.f + __expf(-fabsf(c1)));
        linB  += fmaxf(c2, 0.f) + fmaxf(c3, 0.f);
        prodB *= (1.f + __expf(-fabsf(c2))) * (1.f + __expf(-fabsf(c3)));
    }
    // 32 softplus per row-half in this thread: lin + log(prod), prod <= 2^32
    float sAr = linA + __logf(prodA);
    float sBr = linB + __logf(prodB);

    // reduce across the 4 lanes of the quad that share each row
    sAr += __shfl_xor_sync(0xffffffffu, sAr, 1);
    sAr += __shfl_xor_sync(0xffffffffu, sAr, 2);
    sBr += __shfl_xor_sync(0xffffffffu, sBr, 1);
    sBr += __shfl_xor_sync(0xffffffffu, sBr, 2);
    if (four == 0) {
        g_partial[q * NN + rA] = sAr;
        g_partial[q * NN + rB] = sBr;
    }

    // ---- last-block finalize (threadFenceReduction pattern) ----
    __threadfence();                                 // publish partials + diag
    __syncthreads();
    if (tid == 0) {
        unsigned old = atomicAdd(&g_ticket, 1u);
        s_last = ((old & 255u) == 255u) ? 1u : 0u;   // grid == 256 exactly
    }
    __syncthreads();
    if (s_last) {
        __threadfence();                             // acquire others' writes
        #pragma unroll
        for (int r = 0; r < 8; r++) {
            const int i = tid + r * 256;
            float tot = 0.f;
            #pragma unroll
            for (int p = 0; p < 16; p++) tot += g_partial[p * NN + i];
            float ud  = g_diag[i];
            float spd = softplus_f(ud);
            float Eneg = (tot - spd - 2047.f * LOG2F_) * (1.f / 2047.f);
            float Epos = LOG2F_ - spd + ud;          // = log2 - softplus(-u_ii)
            out[i]      = Eneg - Epos;               // loss
            out[NN + i] = Epos;                      // MI
        }
    }
}

extern "C" void kernel_launch(void* const* d_in, const int* in_sizes, int n_in,
                              void* d_out, int out_size) {
    const float* state  = (const float*)d_in[0];
    const float* action = (const float*)d_in[1];
    const float* W1     = (const float*)d_in[2];
    const float* b1     = (const float*)d_in[3];
    const float* W2     = (const float*)d_in[4];
    const float* b2     = (const float*)d_in[5];
    float* out = (float*)d_out;

    embed_kernel<<<NN / 4, 256>>>(state, action, W1, b1, W2, b2);
    jsd_kernel<<<256, 256>>>(out);
}